// round 16
// baseline (speedup 1.0000x reference)
#include <cuda_runtime.h>
#include <cuda_fp16.h>
#include <cstdint>

// ---------------------------------------------------------------------------
// GraphSAGE with LSTM aggregation, 3 layers — round 15.
// Fused LSTM identified as MUFU-bound (5 tanh.approx.f32 per cell). This
// round: all activations via packed tanh.approx.f16x2 (2 cells per MUFU op),
// c kept fp32, h produced directly in fp16. MUFU per cell halved.
// ---------------------------------------------------------------------------

#define NN   50000
#define DEG  16
#define FDIM 128
#define GDIM 512
#define BMF  64

__device__ uint4 g_Whk[8320];      // fused B: Whh fp16 [k][520] (gate-permuted n)
__device__ uint4 g_Wik[8320];      // pre  B: Wih fp16 [k][520] (original n)
__device__ uint4 g_Wout[4352];     // out  B: [Wl|Wr] fp16 [256][136 or 72]
__device__ uint4 g_Xh[800000];     // layer input fp16 [m][128]
__device__ uint4 g_Hh[800000];     // aggr h fp16 [m][128]
__device__ uint4 g_Pp[3200000];    // P fp16, permuted [m][512]

// fused SMEM (bytes): B 133120 | A 2 bufs x 17408 | src ids 4096
#define SM_B     0
#define SM_A     133120
#define SM_SS    167936
#define SM_TOTAL 172032

// pre SMEM: A 34816 | B 34816 | Ptile 128 x 1056 B = 135168  -> 204800 total
#define PRE_A    0
#define PRE_B    34816
#define PRE_PT   69632
#define PRE_TOT  204800
#define PT_ROW   1056

// ---- activations ------------------------------------------------------------
__device__ __forceinline__ float htanh(float x) {
    float y;
    asm("tanh.approx.f32 %0, %1;" : "=f"(y) : "f"(x));
    return y;
}
__device__ __forceinline__ float fsig(float x) {
    return fmaf(0.5f, htanh(0.5f * x), 0.5f);
}
__device__ __forceinline__ uint32_t h2tanh_u(uint32_t x) {
    uint32_t y;
    asm("tanh.approx.f16x2 %0, %1;" : "=r"(y) : "r"(x));
    return y;
}
__device__ __forceinline__ uint32_t pack_h2(float a, float b) {
    uint32_t r;
    asm("cvt.rn.f16x2.f32 %0, %1, %2;" : "=r"(r) : "f"(b), "f"(a));
    return r;
}

// ---- cp.async --------------------------------------------------------------
__device__ __forceinline__ void cp16(uint32_t saddr, const void* gaddr) {
    asm volatile("cp.async.cg.shared.global [%0], [%1], 16;"
                 :: "r"(saddr), "l"(gaddr));
}
__device__ __forceinline__ void cp_commit() { asm volatile("cp.async.commit_group;"); }
__device__ __forceinline__ void cp_wait0()  { asm volatile("cp.async.wait_group 0;"); }

// ---- mma / ldmatrix --------------------------------------------------------
__device__ __forceinline__ void mma16816(float* d, const uint32_t* a,
                                         uint32_t b0, uint32_t b1) {
    asm volatile(
        "mma.sync.aligned.m16n8k16.row.col.f32.f16.f16.f32 "
        "{%0,%1,%2,%3},{%4,%5,%6,%7},{%8,%9},{%0,%1,%2,%3};"
        : "+f"(d[0]), "+f"(d[1]), "+f"(d[2]), "+f"(d[3])
        : "r"(a[0]), "r"(a[1]), "r"(a[2]), "r"(a[3]), "r"(b0), "r"(b1));
}
__device__ __forceinline__ void ldsm4(uint32_t* r, uint32_t a) {
    asm volatile("ldmatrix.sync.aligned.m8n8.x4.shared.b16 {%0,%1,%2,%3}, [%4];"
                 : "=r"(r[0]), "=r"(r[1]), "=r"(r[2]), "=r"(r[3]) : "r"(a));
}
__device__ __forceinline__ void ldsm4t(uint32_t* r, uint32_t a) {
    asm volatile("ldmatrix.sync.aligned.m8n8.x4.trans.shared.b16 {%0,%1,%2,%3}, [%4];"
                 : "=r"(r[0]), "=r"(r[1]), "=r"(r[2]), "=r"(r[3]) : "r"(a));
}
__device__ __forceinline__ uint32_t packh2(__half a, __half b) {
    return ((uint32_t)__half_as_ushort(b) << 16) | (uint32_t)__half_as_ushort(a);
}

// ---------------------------------------------------------------------------
// conversion kernels
// ---------------------------------------------------------------------------
__global__ void conv_x(const float* __restrict__ x)
{
    int i = blockIdx.x * blockDim.x + threadIdx.x;
    if (i >= NN * 64) return;
    float2 v = ((const float2*)x)[i];
    ((__half2*)g_Xh)[i] = __floats2half2_rn(v.x, v.y);
}

__global__ void conv_weights(const float* __restrict__ Whh,
                             const float* __restrict__ Wih,
                             const float* __restrict__ Wl,
                             const float* __restrict__ Wr, int FO, int BPAD)
{
    int idx = blockIdx.x * blockDim.x + threadIdx.x;
    if (idx < GDIM * FDIM) {
        int r = idx >> 7, k = idx & 127;
        int g = r >> 7, w = (r >> 4) & 7, f = r & 15;
        int n = w * 64 + g * 16 + f;
        ((__half*)g_Whk)[k * 520 + n] = __float2half_rn(Whh[idx]);
    } else if (idx < 2 * GDIM * FDIM) {
        int j = idx - GDIM * FDIM;
        int n = j >> 7, k = j & 127;
        ((__half*)g_Wik)[k * 520 + n] = __float2half_rn(Wih[j]);
    } else if (idx < 2 * GDIM * FDIM + FO * 256) {
        int j = idx - 2 * GDIM * FDIM;
        int n = j >> 8, k = j & 255;
        float v = (k < 128) ? Wl[n * 128 + k] : Wr[n * 128 + (k - 128)];
        ((__half*)g_Wout)[k * BPAD + n] = __float2half_rn(v);
    }
}

// ---------------------------------------------------------------------------
// pre_mma (unchanged from round 13)
// ---------------------------------------------------------------------------
__global__ __launch_bounds__(256)
void pre_mma(const float* __restrict__ bih, const float* __restrict__ bhh)
{
    extern __shared__ char sm[];
    const uint32_t smb = (uint32_t)__cvta_generic_to_shared(sm);
    const uint32_t Asm = smb + PRE_A, Bsm = smb + PRE_B, Pts = smb + PRE_PT;
    const int tid = threadIdx.x, wid = tid >> 5, lane = tid & 31;
    const int m0 = blockIdx.x * 128;

    for (int i = tid; i < 2048; i += 256) {
        int r = i >> 4, j = i & 15;
        int node = m0 + r; if (node >= NN) node = NN - 1;
        cp16(Asm + (uint32_t)(r * 272 + j * 16),
             (const char*)g_Xh + (size_t)node * 256 + j * 16);
    }
    for (int i = tid; i < 2048; i += 256) {
        int r = i >> 4, j = i & 15;
        cp16(Bsm + (uint32_t)(r * 272 + j * 16),
             (const char*)g_Wik + (size_t)r * 1040 + j * 16);
    }
    cp_commit(); cp_wait0(); __syncthreads();

    const int wm = wid >> 2, wn = wid & 3;
    const int aRow = ((lane >> 3) & 1) * 8 + (lane & 7);
    const int aCol = (lane >> 4) * 16;
    const int bRow = aRow;
    const int bCol = ((lane >> 4) & 1) * 16;
    const int grp = lane >> 2, tig = lane & 3;

#pragma unroll 1
    for (int y = 0; y < 4; y++) {
        float acc[4][4][4];
#pragma unroll
        for (int a = 0; a < 4; a++)
#pragma unroll
            for (int b = 0; b < 4; b++)
#pragma unroll
                for (int q = 0; q < 4; q++) acc[a][b][q] = 0.f;

#pragma unroll
        for (int kt = 0; kt < 8; kt++) {
            uint32_t bfr[2][4];
#pragma unroll
            for (int q = 0; q < 2; q++)
                ldsm4t(bfr[q], Bsm + (uint32_t)((kt * 16 + bRow) * 272 +
                       (wn * 32 + q * 16) * 2 + bCol));
#pragma unroll
            for (int mt = 0; mt < 4; mt++) {
                uint32_t af[4];
                ldsm4(af, Asm + (uint32_t)((wm * 64 + mt * 16 + aRow) * 272 +
                       kt * 32 + aCol));
#pragma unroll
                for (int nt = 0; nt < 4; nt++)
                    mma16816(acc[mt][nt], af, bfr[nt >> 1][(nt & 1) * 2],
                             bfr[nt >> 1][(nt & 1) * 2 + 1]);
            }
        }

#pragma unroll
        for (int nt = 0; nt < 4; nt++) {
            int n = y * 128 + wn * 32 + nt * 8 + 2 * tig;
            float b0 = bih[n] + bhh[n];
            float b1 = bih[n + 1] + bhh[n + 1];
            int w = (n >> 4) & 7, f = n & 15;
            int dsti = w * 64 + ((f >> 1) & 3) * 16 + y * 4 + (f >> 3) * 2;
#pragma unroll
            for (int mt = 0; mt < 4; mt++) {
                int r0 = wm * 64 + mt * 16 + grp;
                uint32_t a0 = Pts + (uint32_t)(r0 * PT_ROW + dsti * 2);
                uint32_t v0 = packh2(__float2half_rn(acc[mt][nt][0] + b0),
                                     __float2half_rn(acc[mt][nt][1] + b1));
                asm volatile("st.shared.b32 [%0], %1;" :: "r"(a0), "r"(v0));
                uint32_t a1 = a0 + 8 * PT_ROW;
                uint32_t v1 = packh2(__float2half_rn(acc[mt][nt][2] + b0),
                                     __float2half_rn(acc[mt][nt][3] + b1));
                asm volatile("st.shared.b32 [%0], %1;" :: "r"(a1), "r"(v1));
            }
        }

        if (y < 3) {
            __syncthreads();
            for (int i = tid; i < 2048; i += 256) {
                int r = i >> 4, j = i & 15;
                cp16(Bsm + (uint32_t)(r * 272 + j * 16),
                     (const char*)g_Wik + (size_t)r * 1040 +
                     (y + 1) * 256 + j * 16);
            }
            cp_commit(); cp_wait0(); __syncthreads();
        }
    }
    __syncthreads();

    for (int q = tid; q < 8192; q += 256) {
        int row = q >> 6, off = q & 63;
        if (m0 + row < NN) {
            uint4 v;
            uint32_t sa = Pts + (uint32_t)(row * PT_ROW + off * 16);
            asm volatile("ld.shared.v4.u32 {%0,%1,%2,%3}, [%4];"
                         : "=r"(v.x), "=r"(v.y), "=r"(v.z), "=r"(v.w) : "r"(sa));
            g_Pp[(size_t)(m0 + row) * 64 + off] = v;
        }
    }
}

// ---------------------------------------------------------------------------
// pointwise LSTM row update (gate order i,f,g,o), packed f16x2 activations.
// sig(x) = 0.5 + 0.5*tanh(0.5x) in half2; c kept fp32; h emitted as fp16x2.
// ---------------------------------------------------------------------------
template<bool WACC>
__device__ __forceinline__ void pw_row(const float (*am)[4], int rsel,
                                       float* cc, uint4 cur0, uint4 cur1,
                                       uint32_t aw, uint32_t* ghp)
{
    uint4 pfv[2]; pfv[0] = cur0; pfv[1] = cur1;
    const __half2* hp = (const __half2*)pfv;
#pragma unroll
    for (int fp = 0; fp < 2; fp++) {
        float2 PI = __half22float2(hp[0 + fp]);
        float2 PF = __half22float2(hp[2 + fp]);
        float2 PG = __half22float2(hp[4 + fp]);
        float2 PO = __half22float2(hp[6 + fp]);
        if (WACC) {
            PI.x += am[0 + fp][rsel * 2 + 0]; PI.y += am[0 + fp][rsel * 2 + 1];
            PF.x += am[2 + fp][rsel * 2 + 0]; PF.y += am[2 + fp][rsel * 2 + 1];
            PG.x += am[4 + fp][rsel * 2 + 0]; PG.y += am[4 + fp][rsel * 2 + 1];
            PO.x += am[6 + fp][rsel * 2 + 0]; PO.y += am[6 + fp][rsel * 2 + 1];
        }
        // packed activations: 4 MUFU for gates
        uint32_t ti = h2tanh_u(pack_h2(0.5f * PI.x, 0.5f * PI.y));
        uint32_t tf = h2tanh_u(pack_h2(0.5f * PF.x, 0.5f * PF.y));
        uint32_t to = h2tanh_u(pack_h2(0.5f * PO.x, 0.5f * PO.y));
        uint32_t tg = h2tanh_u(pack_h2(PG.x, PG.y));

        const __half2 HF = __floats2half2_rn(0.5f, 0.5f);
        __half2 si = __hfma2(*(__half2*)&ti, HF, HF);
        __half2 sf = __hfma2(*(__half2*)&tf, HF, HF);
        __half2 so = __hfma2(*(__half2*)&to, HF, HF);

        // c update in fp32
        float2 sif = __half22float2(si);
        float2 sff = __half22float2(sf);
        float2 tgf = __half22float2(*(__half2*)&tg);
        float c0 = fmaf(sff.x, cc[fp * 2 + 0], sif.x * tgf.x);
        float c1 = fmaf(sff.y, cc[fp * 2 + 1], sif.y * tgf.y);
        cc[fp * 2 + 0] = c0;
        cc[fp * 2 + 1] = c1;

        // h = sig(o) * tanh(c), emitted directly as fp16x2 (5th MUFU)
        uint32_t tc = h2tanh_u(pack_h2(c0, c1));
        __half2 hh = __hmul2(so, *(__half2*)&tc);
        uint32_t hipk = *(uint32_t*)&hh;
        asm volatile("st.shared.b32 [%0], %1;" :: "r"(aw + fp * 16), "r"(hipk));
        if (ghp) ghp[fp * 4] = hipk;
    }
}

// ---------------------------------------------------------------------------
// Fused LSTM, pipelined (round-14 structure). 782 blocks x 256 threads.
// ---------------------------------------------------------------------------
__global__ __launch_bounds__(256, 1)
void fused_lstm_mma(const int* __restrict__ src)
{
    extern __shared__ char sm[];
    const uint32_t smb = (uint32_t)__cvta_generic_to_shared(sm);
    const uint32_t Bk  = smb + SM_B;
    int* Ss = (int*)(sm + SM_SS);

    const int tid  = threadIdx.x;
    const int wid  = tid >> 5;
    const int lane = tid & 31;
    const int grp  = lane >> 2;
    const int tig  = lane & 3;
    const int m0   = blockIdx.x * BMF;

#pragma unroll
    for (int r = 0; r < 33; r++) {
        int q = tid + 256 * r;
        if (q < 8320) cp16(Bk + (uint32_t)q * 16, g_Whk + q);
    }
    cp_commit();

    for (int i = tid; i < BMF * DEG; i += 256) {
        int node = m0 + i / DEG;
        Ss[i] = (node < NN) ? src[node * DEG + i % DEG] : 0;
    }
    __syncthreads();

    float c[32];
#pragma unroll
    for (int i = 0; i < 32; i++) c[i] = 0.f;

    const int aRow = ((lane >> 3) & 1) * 8 + (lane & 7);
    const int aCol = (lane >> 4) * 16;
    const int bRow = aRow;
    const int bCol = ((lane >> 4) & 1) * 16;

#define PREF(j, slot) do {                                                    \
        int _ml = ((j) >> 1) * 16 + grp + ((j) & 1) * 8;                      \
        const uint4* _pb = g_Pp +                                             \
            ((size_t)Ss[_ml * DEG + t] * 64 + wid * 8 + tig * 2);             \
        pf[slot][0] = _pb[0]; pf[slot][1] = _pb[1];                           \
    } while (0)

#define ROWARGS(j)                                                            \
        const int ml = ((j) >> 1) * 16 + grp + ((j) & 1) * 8;                 \
        const int node = m0 + ml;                                             \
        uint32_t* ghp = (t == DEG - 1 && node < NN)                           \
            ? (uint32_t*)((__half*)g_Hh + (size_t)node * 128 +                \
                          wid * 16 + 2 * tig) : nullptr;                      \
        const uint32_t aw = Awr + (uint32_t)(ml * 272 +                       \
                          (wid * 16 + 2 * tig) * 2);

#pragma unroll 1
    for (int t = 0; t < DEG; t++) {
        const uint32_t Ard = smb + SM_A + (uint32_t)((t & 1) * 17408);
        const uint32_t Awr = smb + SM_A + (uint32_t)(((t + 1) & 1) * 17408);

        uint4 pf[2][2];
        PREF(0, 0);

        if (t > 0) {
            float acc0[2][8][4], acc1[2][8][4];
#pragma unroll
            for (int i = 0; i < 2; i++)
#pragma unroll
                for (int j = 0; j < 8; j++)
#pragma unroll
                    for (int q = 0; q < 4; q++) {
                        acc0[i][j][q] = 0.f; acc1[i][j][q] = 0.f;
                    }

            // ph1: mma rows 0-31 (mt 0,1)
#pragma unroll
            for (int kt = 0; kt < 8; kt++) {
                uint32_t bfr[4][4];
#pragma unroll
                for (int q = 0; q < 4; q++)
                    ldsm4t(bfr[q], Bk + (uint32_t)((kt * 16 + bRow) * 1040 +
                           (wid * 64 + q * 16) * 2 + bCol));
#pragma unroll
                for (int mti = 0; mti < 2; mti++) {
                    uint32_t af[4];
                    ldsm4(af, Ard + (uint32_t)((mti * 16 + aRow) * 272 +
                           kt * 32 + aCol));
#pragma unroll
                    for (int nt = 0; nt < 8; nt++)
                        mma16816(acc0[mti][nt], af, bfr[nt >> 1][(nt & 1) * 2],
                                 bfr[nt >> 1][(nt & 1) * 2 + 1]);
                }
                if (kt == 3) PREF(1, 1);
            }

            // ph2: mma rows 32-63 interleaved with pw rows j=0..3
#pragma unroll
            for (int kt = 0; kt < 8; kt++) {
                uint32_t bfr[4][4];
#pragma unroll
                for (int q = 0; q < 4; q++)
                    ldsm4t(bfr[q], Bk + (uint32_t)((kt * 16 + bRow) * 1040 +
                           (wid * 64 + q * 16) * 2 + bCol));
#pragma unroll
                for (int mti = 0; mti < 2; mti++) {
                    uint32_t af[4];
                    ldsm4(af, Ard + (uint32_t)(((2 + mti) * 16 + aRow) * 272 +
                           kt * 32 + aCol));
#pragma unroll
                    for (int nt = 0; nt < 8; nt++)
                        mma16816(acc1[mti][nt], af, bfr[nt >> 1][(nt & 1) * 2],
                                 bfr[nt >> 1][(nt & 1) * 2 + 1]);
                }
                if (kt & 1) {
                    const int j = kt >> 1;
                    uint4 cur0 = pf[j & 1][0], cur1 = pf[j & 1][1];
                    PREF(j + 2, j & 1);
                    ROWARGS(j);
                    pw_row<true>(acc0[j >> 1], j & 1, c + j * 4,
                                 cur0, cur1, aw, ghp);
                }
            }

            // ph3: pw rows j=4..7
#pragma unroll
            for (int j = 4; j < 8; j++) {
                uint4 cur0 = pf[j & 1][0], cur1 = pf[j & 1][1];
                if (j + 2 < 8) PREF(j + 2, j & 1);
                ROWARGS(j);
                pw_row<true>(acc1[(j >> 1) - 2], j & 1, c + j * 4,
                             cur0, cur1, aw, ghp);
            }
        } else {
            PREF(1, 1);
#pragma unroll
            for (int j = 0; j < 8; j++) {
                uint4 cur0 = pf[j & 1][0], cur1 = pf[j & 1][1];
                if (j + 2 < 8) PREF(j + 2, j & 1);
                ROWARGS(j);
                pw_row<false>(nullptr, j & 1, c + j * 4, cur0, cur1, aw, ghp);
            }
        }

        if (t == 0) cp_wait0();
        __syncthreads();
    }
#undef PREF
#undef ROWARGS
}

// ---------------------------------------------------------------------------
// out_mma (unchanged)
// ---------------------------------------------------------------------------
template<int FO, bool RELU>
__global__ __launch_bounds__(256)
void out_mma(const float* __restrict__ bl, float* __restrict__ OutF)
{
    constexpr int BROW = (FO == 128) ? 272 : 144;
    constexpr int BCH  = BROW / 16;
    constexpr int WN   = FO / 32;
    constexpr int MT   = (FO == 128) ? 4 : 2;

    extern __shared__ char sm[];
    const uint32_t smb = (uint32_t)__cvta_generic_to_shared(sm);
    const uint32_t Asm = smb, Bsm = smb + 69632;
    const int tid = threadIdx.x, wid = tid >> 5, lane = tid & 31;
    const int m0 = blockIdx.x * 128;

    for (int i = tid; i < 4096; i += 256) {
        int r = i >> 5, j = i & 31;
        int node = m0 + r; if (node >= NN) node = NN - 1;
        const char* srcp = (j < 16)
            ? (const char*)g_Hh + (size_t)node * 256 + j * 16
            : (const char*)g_Xh + (size_t)node * 256 + (j - 16) * 16;
        cp16(Asm + (uint32_t)(r * 544 + j * 16), srcp);
    }
    for (int i = tid; i < 256 * BCH; i += 256) {
        int r = i / BCH, j = i % BCH;
        cp16(Bsm + (uint32_t)(r * BROW + j * 16),
             (const char*)g_Wout + (size_t)r * BROW + j * 16);
    }
    cp_commit(); cp_wait0(); __syncthreads();

    const int wn = wid % WN, wm = wid / WN;
    const int aRow = ((lane >> 3) & 1) * 8 + (lane & 7);
    const int aCol = (lane >> 4) * 16;
    const int bRow = aRow;
    const int bCol = ((lane >> 4) & 1) * 16;

    float acc[MT][4][4];
#pragma unroll
    for (int a = 0; a < MT; a++)
#pragma unroll
        for (int b = 0; b < 4; b++)
#pragma unroll
            for (int q = 0; q < 4; q++) acc[a][b][q] = 0.f;

#pragma unroll
    for (int kt = 0; kt < 16; kt++) {
        uint32_t bfr[2][4];
#pragma unroll
        for (int q = 0; q < 2; q++)
            ldsm4t(bfr[q], Bsm + (uint32_t)((kt * 16 + bRow) * BROW +
                   (wn * 32 + q * 16) * 2 + bCol));
#pragma unroll
        for (int mt = 0; mt < MT; mt++) {
            uint32_t af[4];
            ldsm4(af, Asm + (uint32_t)((wm * MT * 16 + mt * 16 + aRow) * 544 +
                   kt * 32 + aCol));
#pragma unroll
            for (int nt = 0; nt < 4; nt++)
                mma16816(acc[mt][nt], af, bfr[nt >> 1][(nt & 1) * 2],
                         bfr[nt >> 1][(nt & 1) * 2 + 1]);
        }
    }

    const int grp = lane >> 2, tig = lane & 3;
#pragma unroll
    for (int nt = 0; nt < 4; nt++) {
        int n = wn * 32 + nt * 8 + 2 * tig;
        float b0 = bl[n], b1 = bl[n + 1];
#pragma unroll
        for (int mt = 0; mt < MT; mt++) {
            int r0 = m0 + wm * MT * 16 + mt * 16 + grp;
#pragma unroll
            for (int half = 0; half < 2; half++) {
                int r = r0 + half * 8;
                if (r >= NN) continue;
                float v0 = acc[mt][nt][half * 2 + 0] + b0;
                float v1 = acc[mt][nt][half * 2 + 1] + b1;
                if (RELU) {
                    v0 = fmaxf(v0, 0.f); v1 = fmaxf(v1, 0.f);
                    ((__half2*)g_Xh)[((size_t)r * 128 + n) >> 1] =
                        __floats2half2_rn(v0, v1);
                } else {
                    *(float2*)(OutF + (size_t)r * FO + n) = make_float2(v0, v1);
                }
            }
        }
    }
}

// ---------------------------------------------------------------------------
// host launcher
// ---------------------------------------------------------------------------
extern "C" void kernel_launch(void* const* d_in, const int* in_sizes, int n_in,
                              void* d_out, int out_size)
{
    (void)in_sizes; (void)n_in; (void)out_size;
    const float* x   = (const float*)d_in[0];
    const int*   src = (const int*)d_in[1];

    const float* P[21];
    for (int i = 0; i < 21; i++) P[i] = (const float*)d_in[2 + i];

    static bool attr_set = false;
    if (!attr_set) {
        cudaFuncSetAttribute(fused_lstm_mma,
                             cudaFuncAttributeMaxDynamicSharedMemorySize, SM_TOTAL);
        cudaFuncSetAttribute(pre_mma,
                             cudaFuncAttributeMaxDynamicSharedMemorySize, PRE_TOT);
        cudaFuncSetAttribute(out_mma<128, true>,
                             cudaFuncAttributeMaxDynamicSharedMemorySize, 139264);
        cudaFuncSetAttribute(out_mma<64, false>,
                             cudaFuncAttributeMaxDynamicSharedMemorySize, 106496);
        attr_set = true;
    }

    const dim3 blk(256);

    conv_x<<<(NN * 64 + 255) / 256, blk>>>(x);

    for (int l = 0; l < 3; l++) {
        const float* Wih = P[7 * l + 0];
        const float* Whh = P[7 * l + 1];
        const float* bih = P[7 * l + 2];
        const float* bhh = P[7 * l + 3];
        const float* Wl  = P[7 * l + 4];
        const float* bl  = P[7 * l + 5];
        const float* Wr  = P[7 * l + 6];

        const int FO   = (l < 2) ? 128 : 64;
        const int BPAD = (l < 2) ? 136 : 72;
        const int convN = 2 * GDIM * FDIM + FO * 256;
        conv_weights<<<(convN + 255) / 256, blk>>>(Whh, Wih, Wl, Wr, FO, BPAD);

        pre_mma<<<(NN + 127) / 128, blk, PRE_TOT>>>(bih, bhh);
        fused_lstm_mma<<<(NN + BMF - 1) / BMF, blk, SM_TOTAL>>>(src);

        if (l < 2)
            out_mma<128, true><<<(NN + 127) / 128, blk, 139264>>>(bl, nullptr);
        else
            out_mma<64, false><<<(NN + 127) / 128, blk, 106496>>>(bl, (float*)d_out);
    }
}

// round 17
// speedup vs baseline: 1.5378x; 1.5378x over previous
#include <cuda_runtime.h>
#include <cuda_fp16.h>
#include <cstdint>

// ---------------------------------------------------------------------------
// GraphSAGE with LSTM aggregation, 3 layers — round 16.
// Fused LSTM: f32 activations (R14 bit-identical math), B fragments hoisted
// to registers for the whole kernel (no per-step B ldsm), per-mt chunk
// processing with warp-parity stagger so tensor and MUFU phases of
// co-resident warps overlap.
// ---------------------------------------------------------------------------

#define NN   50000
#define DEG  16
#define FDIM 128
#define GDIM 512
#define BMF  64

__device__ uint4 g_Whk[8320];      // fused B: Whh fp16 [k][520] (gate-permuted n)
__device__ uint4 g_Wik[8320];      // pre  B: Wih fp16 [k][520] (original n)
__device__ uint4 g_Wout[4352];     // out  B: [Wl|Wr] fp16 [256][136 or 72]
__device__ uint4 g_Xh[800000];     // layer input fp16 [m][128]
__device__ uint4 g_Hh[800000];     // aggr h fp16 [m][128]
__device__ uint4 g_Pp[3200000];    // P fp16, permuted [m][512]

// fused SMEM (bytes): B 133120 | A 2 bufs x 17408 | src ids 4096
#define SM_B     0
#define SM_A     133120
#define SM_SS    167936
#define SM_TOTAL 172032

// pre SMEM: A 34816 | B 34816 | Ptile 128 x 1056 B = 135168  -> 204800 total
#define PRE_A    0
#define PRE_B    34816
#define PRE_PT   69632
#define PRE_TOT  204800
#define PT_ROW   1056

// ---- activations (f32 HW tanh; R8-R14 proven) -------------------------------
__device__ __forceinline__ float htanh(float x) {
    float y;
    asm("tanh.approx.f32 %0, %1;" : "=f"(y) : "f"(x));
    return y;
}
__device__ __forceinline__ float fsig(float x) {
    return fmaf(0.5f, htanh(0.5f * x), 0.5f);
}

// ---- cp.async --------------------------------------------------------------
__device__ __forceinline__ void cp16(uint32_t saddr, const void* gaddr) {
    asm volatile("cp.async.cg.shared.global [%0], [%1], 16;"
                 :: "r"(saddr), "l"(gaddr));
}
__device__ __forceinline__ void cp_commit() { asm volatile("cp.async.commit_group;"); }
__device__ __forceinline__ void cp_wait0()  { asm volatile("cp.async.wait_group 0;"); }

// ---- mma / ldmatrix --------------------------------------------------------
__device__ __forceinline__ void mma16816(float* d, const uint32_t* a,
                                         uint32_t b0, uint32_t b1) {
    asm volatile(
        "mma.sync.aligned.m16n8k16.row.col.f32.f16.f16.f32 "
        "{%0,%1,%2,%3},{%4,%5,%6,%7},{%8,%9},{%0,%1,%2,%3};"
        : "+f"(d[0]), "+f"(d[1]), "+f"(d[2]), "+f"(d[3])
        : "r"(a[0]), "r"(a[1]), "r"(a[2]), "r"(a[3]), "r"(b0), "r"(b1));
}
__device__ __forceinline__ void ldsm4(uint32_t* r, uint32_t a) {
    asm volatile("ldmatrix.sync.aligned.m8n8.x4.shared.b16 {%0,%1,%2,%3}, [%4];"
                 : "=r"(r[0]), "=r"(r[1]), "=r"(r[2]), "=r"(r[3]) : "r"(a));
}
__device__ __forceinline__ void ldsm4t(uint32_t* r, uint32_t a) {
    asm volatile("ldmatrix.sync.aligned.m8n8.x4.trans.shared.b16 {%0,%1,%2,%3}, [%4];"
                 : "=r"(r[0]), "=r"(r[1]), "=r"(r[2]), "=r"(r[3]) : "r"(a));
}
__device__ __forceinline__ uint32_t packh2(__half a, __half b) {
    return ((uint32_t)__half_as_ushort(b) << 16) | (uint32_t)__half_as_ushort(a);
}

// ---------------------------------------------------------------------------
// conversion kernels
// ---------------------------------------------------------------------------
__global__ void conv_x(const float* __restrict__ x)
{
    int i = blockIdx.x * blockDim.x + threadIdx.x;
    if (i >= NN * 64) return;
    float2 v = ((const float2*)x)[i];
    ((__half2*)g_Xh)[i] = __floats2half2_rn(v.x, v.y);
}

__global__ void conv_weights(const float* __restrict__ Whh,
                             const float* __restrict__ Wih,
                             const float* __restrict__ Wl,
                             const float* __restrict__ Wr, int FO, int BPAD)
{
    int idx = blockIdx.x * blockDim.x + threadIdx.x;
    if (idx < GDIM * FDIM) {
        int r = idx >> 7, k = idx & 127;
        int g = r >> 7, w = (r >> 4) & 7, f = r & 15;
        int n = w * 64 + g * 16 + f;
        ((__half*)g_Whk)[k * 520 + n] = __float2half_rn(Whh[idx]);
    } else if (idx < 2 * GDIM * FDIM) {
        int j = idx - GDIM * FDIM;
        int n = j >> 7, k = j & 127;
        ((__half*)g_Wik)[k * 520 + n] = __float2half_rn(Wih[j]);
    } else if (idx < 2 * GDIM * FDIM + FO * 256) {
        int j = idx - 2 * GDIM * FDIM;
        int n = j >> 8, k = j & 255;
        float v = (k < 128) ? Wl[n * 128 + k] : Wr[n * 128 + (k - 128)];
        ((__half*)g_Wout)[k * BPAD + n] = __float2half_rn(v);
    }
}

// ---------------------------------------------------------------------------
// pre_mma (unchanged from round 13)
// ---------------------------------------------------------------------------
__global__ __launch_bounds__(256)
void pre_mma(const float* __restrict__ bih, const float* __restrict__ bhh)
{
    extern __shared__ char sm[];
    const uint32_t smb = (uint32_t)__cvta_generic_to_shared(sm);
    const uint32_t Asm = smb + PRE_A, Bsm = smb + PRE_B, Pts = smb + PRE_PT;
    const int tid = threadIdx.x, wid = tid >> 5, lane = tid & 31;
    const int m0 = blockIdx.x * 128;

    for (int i = tid; i < 2048; i += 256) {
        int r = i >> 4, j = i & 15;
        int node = m0 + r; if (node >= NN) node = NN - 1;
        cp16(Asm + (uint32_t)(r * 272 + j * 16),
             (const char*)g_Xh + (size_t)node * 256 + j * 16);
    }
    for (int i = tid; i < 2048; i += 256) {
        int r = i >> 4, j = i & 15;
        cp16(Bsm + (uint32_t)(r * 272 + j * 16),
             (const char*)g_Wik + (size_t)r * 1040 + j * 16);
    }
    cp_commit(); cp_wait0(); __syncthreads();

    const int wm = wid >> 2, wn = wid & 3;
    const int aRow = ((lane >> 3) & 1) * 8 + (lane & 7);
    const int aCol = (lane >> 4) * 16;
    const int bRow = aRow;
    const int bCol = ((lane >> 4) & 1) * 16;
    const int grp = lane >> 2, tig = lane & 3;

#pragma unroll 1
    for (int y = 0; y < 4; y++) {
        float acc[4][4][4];
#pragma unroll
        for (int a = 0; a < 4; a++)
#pragma unroll
            for (int b = 0; b < 4; b++)
#pragma unroll
                for (int q = 0; q < 4; q++) acc[a][b][q] = 0.f;

#pragma unroll
        for (int kt = 0; kt < 8; kt++) {
            uint32_t bfr[2][4];
#pragma unroll
            for (int q = 0; q < 2; q++)
                ldsm4t(bfr[q], Bsm + (uint32_t)((kt * 16 + bRow) * 272 +
                       (wn * 32 + q * 16) * 2 + bCol));
#pragma unroll
            for (int mt = 0; mt < 4; mt++) {
                uint32_t af[4];
                ldsm4(af, Asm + (uint32_t)((wm * 64 + mt * 16 + aRow) * 272 +
                       kt * 32 + aCol));
#pragma unroll
                for (int nt = 0; nt < 4; nt++)
                    mma16816(acc[mt][nt], af, bfr[nt >> 1][(nt & 1) * 2],
                             bfr[nt >> 1][(nt & 1) * 2 + 1]);
            }
        }

#pragma unroll
        for (int nt = 0; nt < 4; nt++) {
            int n = y * 128 + wn * 32 + nt * 8 + 2 * tig;
            float b0 = bih[n] + bhh[n];
            float b1 = bih[n + 1] + bhh[n + 1];
            int w = (n >> 4) & 7, f = n & 15;
            int dsti = w * 64 + ((f >> 1) & 3) * 16 + y * 4 + (f >> 3) * 2;
#pragma unroll
            for (int mt = 0; mt < 4; mt++) {
                int r0 = wm * 64 + mt * 16 + grp;
                uint32_t a0 = Pts + (uint32_t)(r0 * PT_ROW + dsti * 2);
                uint32_t v0 = packh2(__float2half_rn(acc[mt][nt][0] + b0),
                                     __float2half_rn(acc[mt][nt][1] + b1));
                asm volatile("st.shared.b32 [%0], %1;" :: "r"(a0), "r"(v0));
                uint32_t a1 = a0 + 8 * PT_ROW;
                uint32_t v1 = packh2(__float2half_rn(acc[mt][nt][2] + b0),
                                     __float2half_rn(acc[mt][nt][3] + b1));
                asm volatile("st.shared.b32 [%0], %1;" :: "r"(a1), "r"(v1));
            }
        }

        if (y < 3) {
            __syncthreads();
            for (int i = tid; i < 2048; i += 256) {
                int r = i >> 4, j = i & 15;
                cp16(Bsm + (uint32_t)(r * 272 + j * 16),
                     (const char*)g_Wik + (size_t)r * 1040 +
                     (y + 1) * 256 + j * 16);
            }
            cp_commit(); cp_wait0(); __syncthreads();
        }
    }
    __syncthreads();

    for (int q = tid; q < 8192; q += 256) {
        int row = q >> 6, off = q & 63;
        if (m0 + row < NN) {
            uint4 v;
            uint32_t sa = Pts + (uint32_t)(row * PT_ROW + off * 16);
            asm volatile("ld.shared.v4.u32 {%0,%1,%2,%3}, [%4];"
                         : "=r"(v.x), "=r"(v.y), "=r"(v.z), "=r"(v.w) : "r"(sa));
            g_Pp[(size_t)(m0 + row) * 64 + off] = v;
        }
    }
}

// ---------------------------------------------------------------------------
// pointwise LSTM row update (gate order i,f,g,o) — R14 f32 math, bit-exact.
// ---------------------------------------------------------------------------
template<bool WACC>
__device__ __forceinline__ void pw_row(const float (*am)[4], int rsel,
                                       float* cc, uint4 cur0, uint4 cur1,
                                       uint32_t aw, uint32_t* ghp)
{
    uint4 pfv[2]; pfv[0] = cur0; pfv[1] = cur1;
    const __half2* hp = (const __half2*)pfv;
#pragma unroll
    for (int fp = 0; fp < 2; fp++) {
        float2 PI = __half22float2(hp[0 + fp]);
        float2 PF = __half22float2(hp[2 + fp]);
        float2 PG = __half22float2(hp[4 + fp]);
        float2 PO = __half22float2(hp[6 + fp]);
        float hv[2];
#pragma unroll
        for (int p = 0; p < 2; p++) {
            float gi = p ? PI.y : PI.x;
            float gf = p ? PF.y : PF.x;
            float gg = p ? PG.y : PG.x;
            float go = p ? PO.y : PO.x;
            if (WACC) {
                gi += am[0 + fp][rsel * 2 + p];
                gf += am[2 + fp][rsel * 2 + p];
                gg += am[4 + fp][rsel * 2 + p];
                go += am[6 + fp][rsel * 2 + p];
            }
            float cn = fsig(gf) * cc[fp * 2 + p] + fsig(gi) * htanh(gg);
            cc[fp * 2 + p] = cn;
            hv[p] = fsig(go) * htanh(cn);
        }
        uint32_t hipk = packh2(__float2half_rn(hv[0]), __float2half_rn(hv[1]));
        asm volatile("st.shared.b32 [%0], %1;" :: "r"(aw + fp * 16), "r"(hipk));
        if (ghp) ghp[fp * 4] = hipk;
    }
}

// ---------------------------------------------------------------------------
// Fused LSTM: B register-resident, per-mt chunks, warp-parity stagger.
// 782 blocks x 256 threads. Warp w owns permuted cols [w*64, w*64+64).
// Chunk mt: mma(rows mt*16..mt*16+15) then pw rows rsel=0,1.
// Even warps process mt 0,1,2,3; odd warps 2,3,0,1 (pipe overlap).
// ---------------------------------------------------------------------------
__global__ __launch_bounds__(256, 1)
void fused_lstm_mma(const int* __restrict__ src)
{
    extern __shared__ char sm[];
    const uint32_t smb = (uint32_t)__cvta_generic_to_shared(sm);
    const uint32_t Bk  = smb + SM_B;
    int* Ss = (int*)(sm + SM_SS);

    const int tid  = threadIdx.x;
    const int wid  = tid >> 5;
    const int lane = tid & 31;
    const int grp  = lane >> 2;
    const int tig  = lane & 3;
    const int m0   = blockIdx.x * BMF;

#pragma unroll
    for (int r = 0; r < 33; r++) {
        int q = tid + 256 * r;
        if (q < 8320) cp16(Bk + (uint32_t)q * 16, g_Whk + q);
    }
    cp_commit();

    for (int i = tid; i < BMF * DEG; i += 256) {
        int node = m0 + i / DEG;
        Ss[i] = (node < NN) ? src[node * DEG + i % DEG] : 0;
    }
    cp_wait0();
    __syncthreads();

    const int aRow = ((lane >> 3) & 1) * 8 + (lane & 7);
    const int aCol = (lane >> 4) * 16;
    const int bRow = aRow;
    const int bCol = ((lane >> 4) & 1) * 16;

    // hoist B fragments: constant for the whole kernel (128 regs)
    uint32_t bf[8][4][4];
#pragma unroll
    for (int kt = 0; kt < 8; kt++)
#pragma unroll
        for (int q = 0; q < 4; q++)
            ldsm4t(bf[kt][q], Bk + (uint32_t)((kt * 16 + bRow) * 1040 +
                   (wid * 64 + q * 16) * 2 + bCol));

    float c[32];
#pragma unroll
    for (int i = 0; i < 32; i++) c[i] = 0.f;

    const int par2 = (wid & 1) * 2;   // chunk-order stagger by warp parity

#pragma unroll 1
    for (int t = 0; t < DEG; t++) {
        const uint32_t Ard = smb + SM_A + (uint32_t)((t & 1) * 17408);
        const uint32_t Awr = smb + SM_A + (uint32_t)(((t + 1) & 1) * 17408);

#pragma unroll
        for (int ci = 0; ci < 4; ci++) {
            const int mt = (ci + par2) & 3;

            // prefetch P rows for this chunk (2 rows)
            uint4 pf0[2], pf1[2];
            {
                const int ml0 = mt * 16 + grp;
                const uint4* pb0 = g_Pp +
                    ((size_t)Ss[ml0 * DEG + t] * 64 + wid * 8 + tig * 2);
                pf0[0] = pb0[0]; pf0[1] = pb0[1];
                const uint4* pb1 = g_Pp +
                    ((size_t)Ss[(ml0 + 8) * DEG + t] * 64 + wid * 8 + tig * 2);
                pf1[0] = pb1[0]; pf1[1] = pb1[1];
            }

            float acc[8][4];
#pragma unroll
            for (int j = 0; j < 8; j++)
#pragma unroll
                for (int q = 0; q < 4; q++) acc[j][q] = 0.f;

            if (t > 0) {
#pragma unroll
                for (int kt = 0; kt < 8; kt++) {
                    uint32_t af[4];
                    ldsm4(af, Ard + (uint32_t)((mt * 16 + aRow) * 272 +
                           kt * 32 + aCol));
#pragma unroll
                    for (int nt = 0; nt < 8; nt++)
                        mma16816(acc[nt], af, bf[kt][nt >> 1][(nt & 1) * 2],
                                 bf[kt][nt >> 1][(nt & 1) * 2 + 1]);
                }
            }

            // pointwise rows rsel = 0, 1
#pragma unroll
            for (int rsel = 0; rsel < 2; rsel++) {
                const int ml   = mt * 16 + grp + rsel * 8;
                const int node = m0 + ml;
                uint32_t* ghp = (t == DEG - 1 && node < NN)
                    ? (uint32_t*)((__half*)g_Hh + (size_t)node * 128 +
                                  wid * 16 + 2 * tig) : nullptr;
                const uint32_t aw = Awr + (uint32_t)(ml * 272 +
                                    (wid * 16 + 2 * tig) * 2);
                if (t > 0)
                    pw_row<true>(acc, rsel, c + (mt * 2 + rsel) * 4,
                                 rsel ? pf1[0] : pf0[0],
                                 rsel ? pf1[1] : pf0[1], aw, ghp);
                else
                    pw_row<false>(nullptr, rsel, c + (mt * 2 + rsel) * 4,
                                  rsel ? pf1[0] : pf0[0],
                                  rsel ? pf1[1] : pf0[1], aw, ghp);
            }
        }
        __syncthreads();            // A buffer handoff
    }
}

// ---------------------------------------------------------------------------
// out_mma (unchanged)
// ---------------------------------------------------------------------------
template<int FO, bool RELU>
__global__ __launch_bounds__(256)
void out_mma(const float* __restrict__ bl, float* __restrict__ OutF)
{
    constexpr int BROW = (FO == 128) ? 272 : 144;
    constexpr int BCH  = BROW / 16;
    constexpr int WN   = FO / 32;
    constexpr int MT   = (FO == 128) ? 4 : 2;

    extern __shared__ char sm[];
    const uint32_t smb = (uint32_t)__cvta_generic_to_shared(sm);
    const uint32_t Asm = smb, Bsm = smb + 69632;
    const int tid = threadIdx.x, wid = tid >> 5, lane = tid & 31;
    const int m0 = blockIdx.x * 128;

    for (int i = tid; i < 4096; i += 256) {
        int r = i >> 5, j = i & 31;
        int node = m0 + r; if (node >= NN) node = NN - 1;
        const char* srcp = (j < 16)
            ? (const char*)g_Hh + (size_t)node * 256 + j * 16
            : (const char*)g_Xh + (size_t)node * 256 + (j - 16) * 16;
        cp16(Asm + (uint32_t)(r * 544 + j * 16), srcp);
    }
    for (int i = tid; i < 256 * BCH; i += 256) {
        int r = i / BCH, j = i % BCH;
        cp16(Bsm + (uint32_t)(r * BROW + j * 16),
             (const char*)g_Wout + (size_t)r * BROW + j * 16);
    }
    cp_commit(); cp_wait0(); __syncthreads();

    const int wn = wid % WN, wm = wid / WN;
    const int aRow = ((lane >> 3) & 1) * 8 + (lane & 7);
    const int aCol = (lane >> 4) * 16;
    const int bRow = aRow;
    const int bCol = ((lane >> 4) & 1) * 16;

    float acc[MT][4][4];
#pragma unroll
    for (int a = 0; a < MT; a++)
#pragma unroll
        for (int b = 0; b < 4; b++)
#pragma unroll
            for (int q = 0; q < 4; q++) acc[a][b][q] = 0.f;

#pragma unroll
    for (int kt = 0; kt < 16; kt++) {
        uint32_t bfr[2][4];
#pragma unroll
        for (int q = 0; q < 2; q++)
            ldsm4t(bfr[q], Bsm + (uint32_t)((kt * 16 + bRow) * BROW +
                   (wn * 32 + q * 16) * 2 + bCol));
#pragma unroll
        for (int mt = 0; mt < MT; mt++) {
            uint32_t af[4];
            ldsm4(af, Asm + (uint32_t)((wm * MT * 16 + mt * 16 + aRow) * 544 +
                   kt * 32 + aCol));
#pragma unroll
            for (int nt = 0; nt < 4; nt++)
                mma16816(acc[mt][nt], af, bfr[nt >> 1][(nt & 1) * 2],
                         bfr[nt >> 1][(nt & 1) * 2 + 1]);
        }
    }

    const int grp = lane >> 2, tig = lane & 3;
#pragma unroll
    for (int nt = 0; nt < 4; nt++) {
        int n = wn * 32 + nt * 8 + 2 * tig;
        float b0 = bl[n], b1 = bl[n + 1];
#pragma unroll
        for (int mt = 0; mt < MT; mt++) {
            int r0 = m0 + wm * MT * 16 + mt * 16 + grp;
#pragma unroll
            for (int half = 0; half < 2; half++) {
                int r = r0 + half * 8;
                if (r >= NN) continue;
                float v0 = acc[mt][nt][half * 2 + 0] + b0;
                float v1 = acc[mt][nt][half * 2 + 1] + b1;
                if (RELU) {
                    v0 = fmaxf(v0, 0.f); v1 = fmaxf(v1, 0.f);
                    ((__half2*)g_Xh)[((size_t)r * 128 + n) >> 1] =
                        __floats2half2_rn(v0, v1);
                } else {
                    *(float2*)(OutF + (size_t)r * FO + n) = make_float2(v0, v1);
                }
            }
        }
    }
}

// ---------------------------------------------------------------------------
// host launcher
// ---------------------------------------------------------------------------
extern "C" void kernel_launch(void* const* d_in, const int* in_sizes, int n_in,
                              void* d_out, int out_size)
{
    (void)in_sizes; (void)n_in; (void)out_size;
    const float* x   = (const float*)d_in[0];
    const int*   src = (const int*)d_in[1];

    const float* P[21];
    for (int i = 0; i < 21; i++) P[i] = (const float*)d_in[2 + i];

    static bool attr_set = false;
    if (!attr_set) {
        cudaFuncSetAttribute(fused_lstm_mma,
                             cudaFuncAttributeMaxDynamicSharedMemorySize, SM_TOTAL);
        cudaFuncSetAttribute(pre_mma,
                             cudaFuncAttributeMaxDynamicSharedMemorySize, PRE_TOT);
        cudaFuncSetAttribute(out_mma<128, true>,
                             cudaFuncAttributeMaxDynamicSharedMemorySize, 139264);
        cudaFuncSetAttribute(out_mma<64, false>,
                             cudaFuncAttributeMaxDynamicSharedMemorySize, 106496);
        attr_set = true;
    }

    const dim3 blk(256);

    conv_x<<<(NN * 64 + 255) / 256, blk>>>(x);

    for (int l = 0; l < 3; l++) {
        const float* Wih = P[7 * l + 0];
        const float* Whh = P[7 * l + 1];
        const float* bih = P[7 * l + 2];
        const float* bhh = P[7 * l + 3];
        const float* Wl  = P[7 * l + 4];
        const float* bl  = P[7 * l + 5];
        const float* Wr  = P[7 * l + 6];

        const int FO   = (l < 2) ? 128 : 64;
        const int BPAD = (l < 2) ? 136 : 72;
        const int convN = 2 * GDIM * FDIM + FO * 256;
        conv_weights<<<(convN + 255) / 256, blk>>>(Whh, Wih, Wl, Wr, FO, BPAD);

        pre_mma<<<(NN + 127) / 128, blk, PRE_TOT>>>(bih, bhh);
        fused_lstm_mma<<<(NN + BMF - 1) / BMF, blk, SM_TOTAL>>>(src);

        if (l < 2)
            out_mma<128, true><<<(NN + 127) / 128, blk, 139264>>>(bl, nullptr);
        else
            out_mma<64, false><<<(NN + 127) / 128, blk, 106496>>>(bl, (float*)d_out);
    }
}